// round 14
// baseline (speedup 1.0000x reference)
#include <cuda_runtime.h>
#include <cuda_bf16.h>
#include <cstdint>

#define N_NODES 100000
#define HDIM 128
#define H2DIM 256
#define N_EDGES 600000
#define NSUB 20000
#define ESUB 200000
#define NLAYERS 3
#define NSUBT 2
#define OUTDIM 128

#define CSR_R 340000
#define CSR_E 1400000
#define NBLK_SCAN 333
#define B_S0C 100000
#define B_S0R 120000
#define B_S1C 220000
#define B_S1R 240000

// ---------------- persistent scratch ----------------------------------------
__device__ float g_x   [N_NODES * HDIM];
__device__ float g_h   [N_NODES * H2DIM];
__device__ float g_sx  [NSUB * HDIM];
__device__ float g_sxh [NSUB * H2DIM];
__device__ float g_sx2 [NSUB * HDIM];
__device__ float g_sum  [H2DIM];
__device__ float g_sumsq[H2DIM];
__device__ float g_scale[H2DIM];
__device__ float g_shift[H2DIM];
#define W_TOTAL 1048576
__device__ __nv_bfloat16 g_whi[W_TOTAL];
__device__ __nv_bfloat16 g_wlo[W_TOTAL];
__device__ int g_cnt2   [CSR_R];
__device__ int g_cursor2[CSR_R];
__device__ int g_offs   [CSR_R + 1];
__device__ int g_part   [NBLK_SCAN + 1];
__device__ int g_csr    [CSR_E];

// ---------------- batched CSR build ------------------------------------------
__device__ __forceinline__ void edge_decode(int e, const int* __restrict__ edge,
                                            const int* __restrict__ se0,
                                            const int* __restrict__ se1,
                                            int& d, int& s) {
    if (e < N_EDGES) { d = __ldg(edge + N_EDGES + e); s = __ldg(edge + e); return; }
    e -= N_EDGES;
    if (e < ESUB) { d = B_S0C + __ldg(se0 + ESUB + e); s = __ldg(se0 + e); return; }
    e -= ESUB;
    if (e < ESUB) { d = B_S0R + __ldg(se0 + e); s = __ldg(se0 + ESUB + e); return; }
    e -= ESUB;
    if (e < ESUB) { d = B_S1C + __ldg(se1 + ESUB + e); s = __ldg(se1 + e); return; }
    e -= ESUB;
    d = B_S1R + __ldg(se1 + e); s = __ldg(se1 + ESUB + e);
}
__global__ void k_hist_all(const int* __restrict__ edge, const int* __restrict__ se0,
                           const int* __restrict__ se1, int* __restrict__ cnt) {
    int e = blockIdx.x * blockDim.x + threadIdx.x;
    if (e >= CSR_E) return;
    int d, s;
    edge_decode(e, edge, se0, se1, d, s);
    atomicAdd(&cnt[d], 1);
}
__global__ void k_fill_all(const int* __restrict__ edge, const int* __restrict__ se0,
                           const int* __restrict__ se1, int* __restrict__ cursor,
                           int* __restrict__ csr) {
    int e = blockIdx.x * blockDim.x + threadIdx.x;
    if (e >= CSR_E) return;
    int d, s;
    edge_decode(e, edge, se0, se1, d, s);
    int pos = atomicAdd(&cursor[d], 1);
    csr[pos] = s;
}
__device__ __forceinline__ int block_excl_scan(int v) {
    __shared__ int ws[32];
    int lane = threadIdx.x & 31, w = threadIdx.x >> 5;
    int x = v;
#pragma unroll
    for (int d = 1; d < 32; d <<= 1) {
        int y = __shfl_up_sync(0xFFFFFFFFu, x, d);
        if (lane >= d) x += y;
    }
    if (lane == 31) ws[w] = x;
    __syncthreads();
    if (w == 0) {
        int s = ws[lane];
#pragma unroll
        for (int d = 1; d < 32; d <<= 1) {
            int y = __shfl_up_sync(0xFFFFFFFFu, s, d);
            if (lane >= d) s += y;
        }
        ws[lane] = s;
    }
    __syncthreads();
    int woff = (w > 0) ? ws[w - 1] : 0;
    return x - v + woff;
}
__global__ void k_scanA(const int* __restrict__ cnt, int* __restrict__ offs,
                        int* __restrict__ part) {
    int idx = blockIdx.x * 1024 + threadIdx.x;
    int v = (idx < CSR_R) ? cnt[idx] : 0;
    int excl = block_excl_scan(v);
    if (idx < CSR_R) offs[idx] = excl;
    if (threadIdx.x == 1023) part[blockIdx.x] = excl + v;
}
__global__ void k_scanB(int* __restrict__ part) {
    int i = threadIdx.x;
    int v = (i < NBLK_SCAN) ? part[i] : 0;
    int excl = block_excl_scan(v);
    __syncthreads();
    if (i < NBLK_SCAN) part[i] = excl;
    if (i == NBLK_SCAN - 1) part[NBLK_SCAN] = excl + v;
}
// scanC also restores cnt2 to zero (consumed by scanA) for the next replay.
__global__ void k_scanC(int* __restrict__ offs, const int* __restrict__ part,
                        int* __restrict__ cursor, int* __restrict__ cnt) {
    int idx = blockIdx.x * 1024 + threadIdx.x;
    if (idx < CSR_R) {
        int o = offs[idx] + part[blockIdx.x];
        offs[idx] = o;
        cursor[idx] = o;
        cnt[idx] = 0;
    } else if (idx == CSR_R) {
        offs[CSR_R] = part[NBLK_SCAN];
    }
}

// ---------------- standalone gather (sx only; unroll 4) ------------------------
__global__ void k_gather(float* __restrict__ out, const float* __restrict__ in,
                         const int* __restrict__ offs, const int* __restrict__ srcs,
                         int nrows) {
    int node = blockIdx.x * 8 + (threadIdx.x >> 5);
    if (node >= nrows) return;
    int lane4 = (threadIdx.x & 31) * 4;
    int b = __ldg(offs + node), e = __ldg(offs + node + 1);
    float4 acc = make_float4(0.f, 0.f, 0.f, 0.f);
    int j = b;
    for (; j + 4 <= e; j += 4) {
        int s0 = __ldg(srcs + j + 0), s1 = __ldg(srcs + j + 1);
        int s2 = __ldg(srcs + j + 2), s3 = __ldg(srcs + j + 3);
        float4 v0 = *reinterpret_cast<const float4*>(in + (size_t)s0 * HDIM + lane4);
        float4 v1 = *reinterpret_cast<const float4*>(in + (size_t)s1 * HDIM + lane4);
        float4 v2 = *reinterpret_cast<const float4*>(in + (size_t)s2 * HDIM + lane4);
        float4 v3 = *reinterpret_cast<const float4*>(in + (size_t)s3 * HDIM + lane4);
        acc.x += (v0.x + v1.x) + (v2.x + v3.x);
        acc.y += (v0.y + v1.y) + (v2.y + v3.y);
        acc.z += (v0.z + v1.z) + (v2.z + v3.z);
        acc.w += (v0.w + v1.w) + (v2.w + v3.w);
    }
    for (; j < e; j++) {
        int s = __ldg(srcs + j);
        float4 v = *reinterpret_cast<const float4*>(in + (size_t)s * HDIM + lane4);
        acc.x += v.x; acc.y += v.y; acc.z += v.z; acc.w += v.w;
    }
    *reinterpret_cast<float4*>(out + (size_t)node * HDIM + lane4) = acc;
}

// ---------------- BN finalize (R12 style) ---------------------------------------
__global__ void k_bnfin(const float* __restrict__ gamma, const float* __restrict__ beta,
                        float invM) {
    int c = threadIdx.x;
    float mean = g_sum[c] * invM;
    float var  = g_sumsq[c] * invM - mean * mean;
    float sc   = __ldg(gamma + c) * rsqrtf(var + 1e-5f);
    g_scale[c] = sc;
    g_shift[c] = __ldg(beta + c) - mean * sc;
    g_sum[c] = 0.f;
    g_sumsq[c] = 0.f;
}

// ---------------- single-launch weight prep (also zeroes BN stats) -----------
__global__ void k_prep_all(const float* __restrict__ w0, const float* __restrict__ w1,
                           const float* __restrict__ w2, const float* __restrict__ w3,
                           const float* __restrict__ w4, const float* __restrict__ w5,
                           const float* __restrict__ w6, const float* __restrict__ w7,
                           __nv_bfloat16* __restrict__ hi, __nv_bfloat16* __restrict__ lo) {
    int i = blockIdx.x * blockDim.x + threadIdx.x;
    if (i < H2DIM) { g_sum[i] = 0.f; g_sumsq[i] = 0.f; }
    if (i >= W_TOTAL) return;
    const float* src;
    int base, K, Nw;
    if      (i < 98304)   { src = w0; base = 0;       K = 128; Nw = 256; }
    else if (i < 196608)  { src = w1; base = 98304;   K = 256; Nw = 128; }
    else if (i < 393216)  { src = w2; base = 196608;  K = 128; Nw = 256; }
    else if (i < 589824)  { src = w3; base = 393216;  K = 256; Nw = 128; }
    else if (i < 786432)  { src = w4; base = 589824;  K = 128; Nw = 256; }
    else if (i < 983040)  { src = w5; base = 786432;  K = 256; Nw = 128; }
    else if (i < 1015808) { src = w6; base = 983040;  K = 128; Nw = 256; }
    else                  { src = w7; base = 1015808; K = 256; Nw = 128; }
    int local = i - base;
    int per = K * Nw;
    int m = local / per, r = local % per;
    int k = r / Nw, n = r % Nw;
    float w = __ldg(src + local);
    __nv_bfloat16 h = __float2bfloat16(w);
    float res = w - __bfloat162float(h);
    int o = base + m * per + n * K + k;
    hi[o] = h;
    lo[o] = __float2bfloat16(res);
}

// ---------------- mma.sync helpers ------------------------------------------
__device__ __forceinline__ uint32_t smem_u32(const void* p) {
    uint32_t a;
    asm("{ .reg .u64 t; cvta.to.shared.u64 t, %1; cvt.u32.u64 %0, t; }" : "=r"(a) : "l"(p));
    return a;
}
__device__ __forceinline__ void ldsm_x4(uint32_t* r, uint32_t addr) {
    asm volatile("ldmatrix.sync.aligned.m8n8.x4.shared.b16 {%0,%1,%2,%3}, [%4];"
                 : "=r"(r[0]), "=r"(r[1]), "=r"(r[2]), "=r"(r[3]) : "r"(addr));
}
__device__ __forceinline__ void mma16816(float* d, const uint32_t* a, uint32_t b0, uint32_t b1) {
    asm volatile(
        "mma.sync.aligned.m16n8k16.row.col.f32.bf16.bf16.f32 "
        "{%0,%1,%2,%3}, {%4,%5,%6,%7}, {%8,%9}, {%0,%1,%2,%3};"
        : "+f"(d[0]), "+f"(d[1]), "+f"(d[2]), "+f"(d[3])
        : "r"(a[0]), "r"(a[1]), "r"(a[2]), "r"(a[3]), "r"(b0), "r"(b1));
}
__device__ __forceinline__ void cp_async16(uint32_t dst, const void* src) {
    asm volatile("cp.async.cg.shared.global [%0], [%1], 16;" :: "r"(dst), "l"(src));
}
__device__ __forceinline__ uint32_t soff32(int r, int c16) {
    return (uint32_t)r * 64u + (uint32_t)((c16 ^ ((r >> 1) & 3)) << 4);
}
__device__ __forceinline__ void split2(float x, float y, uint32_t& hp, uint32_t& lp) {
    __nv_bfloat162 h = __float22bfloat162_rn(make_float2(x, y));
    float2 f = __bfloat1622float2(h);
    __nv_bfloat162 l = __float22bfloat162_rn(make_float2(x - f.x, y - f.y));
    hp = *(uint32_t*)&h;
    lp = *(uint32_t*)&l;
}

// ---------------- pipelined mma.sync split-bf16 GEMM -------------------------
// 3-stage cp.async pipeline, K=32 per stage, 96KB total, occupancy 2 (R12).
// AOP: 0 identity fp32 A ; 1 relu(A*scale+shift) BN-fused A ;
//      3 A[row] = CSR-gathered sum of source rows ;
//      4 AOP3 + (1+eps[layer])*source[row] base term (GIN)
// EOP: 0 +bias ; 1 relu(+bias) ; 2 C += acc+bias
// STATS: fused BN column statistics into g_sum/g_sumsq
#define S_AHI 0
#define S_ALO 8192
#define S_BHI 16384
#define S_BLO 24576
#define STAGE_BYTES 32768
#define NSTAGE 3
#define GEMM_SMEM (STAGE_BYTES * NSTAGE)

template <int AOP, int EOP, int STATS>
__global__ __launch_bounds__(256, 2) void k_gemm_mma(
    const float* __restrict__ A, const __nv_bfloat16* __restrict__ Bhi,
    const __nv_bfloat16* __restrict__ Blo, const float* __restrict__ bias,
    float* __restrict__ C, int M, int K, int Nw,
    const float* __restrict__ scale, const float* __restrict__ shift,
    const int* __restrict__ goffs, const int* __restrict__ gcsr,
    const float* __restrict__ epsp, int layer) {
    extern __shared__ char smem[];
    const uint32_t sbase = smem_u32(smem);
    const int tid = threadIdx.x;
    const int wid = tid >> 5;
    const int lane = tid & 31;
    const int row0 = blockIdx.y * 128;
    const int col0 = blockIdx.x * 128;
    const int wm = (wid & 3) * 32;
    const int wn = (wid >> 2) * 64;

    // cache CSR extents for this thread's two fill rows (fixed across stages)
    int gb0 = 0, ge0 = 0, gb1 = 0, ge1 = 0;
    float cf = 0.f;
    if (AOP >= 3) {
        int r0 = tid >> 2, r1 = (tid + 256) >> 2;
        if (row0 + r0 < M) { gb0 = __ldg(goffs + row0 + r0); ge0 = __ldg(goffs + row0 + r0 + 1); }
        if (row0 + r1 < M) { gb1 = __ldg(goffs + row0 + r1); ge1 = __ldg(goffs + row0 + r1 + 1); }
        if (AOP == 4) cf = 1.0f + __ldg(epsp + layer);
    }

    float acc[2][8][4];
#pragma unroll
    for (int i = 0; i < 2; i++)
#pragma unroll
        for (int j = 0; j < 8; j++)
#pragma unroll
            for (int q = 0; q < 4; q++) acc[i][j][q] = 0.f;

    auto fill = [&](int s) {
        int buf = s % NSTAGE;
        char* sb = smem + buf * STAGE_BYTES;
        uint32_t sbu = sbase + (uint32_t)buf * STAGE_BYTES;
        int kof = s * 32;
#pragma unroll
        for (int it = 0; it < 2; it++) {
            int task = tid + it * 256;
            int r = task >> 2, c16 = task & 3;
            uint32_t so = soff32(r, c16);
            cp_async16(sbu + S_BHI + so, Bhi + (size_t)(col0 + r) * K + kof + c16 * 8);
            cp_async16(sbu + S_BLO + so, Blo + (size_t)(col0 + r) * K + kof + c16 * 8);
        }
#pragma unroll
        for (int it = 0; it < 2; it++) {
            int task = tid + it * 256;
            int r = task >> 2, c16 = task & 3;
            uint32_t so = soff32(r, c16);
            float4 v0 = make_float4(0.f, 0.f, 0.f, 0.f), v1 = v0;
            if (AOP >= 3) {
                // CSR-gathered A row slice (K = 128 for these GEMMs)
                int gb = it ? gb1 : gb0;
                int ge = it ? ge1 : ge0;
                int col = kof + c16 * 8;
                if (AOP == 4 && row0 + r < M) {
                    const float* bp = A + (size_t)(row0 + r) * 128 + col;
                    float4 b0 = *reinterpret_cast<const float4*>(bp);
                    float4 b1 = *reinterpret_cast<const float4*>(bp + 4);
                    v0 = make_float4(cf * b0.x, cf * b0.y, cf * b0.z, cf * b0.w);
                    v1 = make_float4(cf * b1.x, cf * b1.y, cf * b1.z, cf * b1.w);
                }
                int j = gb;
                for (; j + 2 <= ge; j += 2) {
                    int s0 = __ldg(gcsr + j), s1 = __ldg(gcsr + j + 1);
                    const float* p0 = A + (size_t)s0 * 128 + col;
                    const float* p1 = A + (size_t)s1 * 128 + col;
                    float4 a0 = *reinterpret_cast<const float4*>(p0);
                    float4 a1 = *reinterpret_cast<const float4*>(p0 + 4);
                    float4 b0 = *reinterpret_cast<const float4*>(p1);
                    float4 b1 = *reinterpret_cast<const float4*>(p1 + 4);
                    v0.x += a0.x + b0.x; v0.y += a0.y + b0.y;
                    v0.z += a0.z + b0.z; v0.w += a0.w + b0.w;
                    v1.x += a1.x + b1.x; v1.y += a1.y + b1.y;
                    v1.z += a1.z + b1.z; v1.w += a1.w + b1.w;
                }
                if (j < ge) {
                    int s0 = __ldg(gcsr + j);
                    const float* p0 = A + (size_t)s0 * 128 + col;
                    float4 a0 = *reinterpret_cast<const float4*>(p0);
                    float4 a1 = *reinterpret_cast<const float4*>(p0 + 4);
                    v0.x += a0.x; v0.y += a0.y; v0.z += a0.z; v0.w += a0.w;
                    v1.x += a1.x; v1.y += a1.y; v1.z += a1.z; v1.w += a1.w;
                }
            } else if (row0 + r < M) {
                const float* ap = A + (size_t)(row0 + r) * K + kof + c16 * 8;
                v0 = *reinterpret_cast<const float4*>(ap);
                v1 = *reinterpret_cast<const float4*>(ap + 4);
                if (AOP == 1) {
                    int gk = kof + c16 * 8;
                    float4 sc0 = *reinterpret_cast<const float4*>(scale + gk);
                    float4 sc1 = *reinterpret_cast<const float4*>(scale + gk + 4);
                    float4 sh0 = *reinterpret_cast<const float4*>(shift + gk);
                    float4 sh1 = *reinterpret_cast<const float4*>(shift + gk + 4);
                    v0.x = fmaxf(fmaf(v0.x, sc0.x, sh0.x), 0.f);
                    v0.y = fmaxf(fmaf(v0.y, sc0.y, sh0.y), 0.f);
                    v0.z = fmaxf(fmaf(v0.z, sc0.z, sh0.z), 0.f);
                    v0.w = fmaxf(fmaf(v0.w, sc0.w, sh0.w), 0.f);
                    v1.x = fmaxf(fmaf(v1.x, sc1.x, sh1.x), 0.f);
                    v1.y = fmaxf(fmaf(v1.y, sc1.y, sh1.y), 0.f);
                    v1.z = fmaxf(fmaf(v1.z, sc1.z, sh1.z), 0.f);
                    v1.w = fmaxf(fmaf(v1.w, sc1.w, sh1.w), 0.f);
                }
            }
            uint32_t h0, l0, h1, l1, h2, l2, h3, l3;
            split2(v0.x, v0.y, h0, l0);
            split2(v0.z, v0.w, h1, l1);
            split2(v1.x, v1.y, h2, l2);
            split2(v1.z, v1.w, h3, l3);
            *reinterpret_cast<uint4*>(sb + S_AHI + so) = make_uint4(h0, h1, h2, h3);
            *reinterpret_cast<uint4*>(sb + S_ALO + so) = make_uint4(l0, l1, l2, l3);
        }
        asm volatile("cp.async.commit_group;" ::: "memory");
    };

    const int nst = K >> 5;
    fill(0);
    if (nst > 1) fill(1);
    for (int s = 0; s < nst; s++) {
        if (s + 2 < nst) {
            fill(s + 2);
            asm volatile("cp.async.wait_group 2;" ::: "memory");
        } else if (s + 1 < nst) {
            asm volatile("cp.async.wait_group 1;" ::: "memory");
        } else {
            asm volatile("cp.async.wait_group 0;" ::: "memory");
        }
        __syncthreads();

        uint32_t sbu = sbase + (uint32_t)(s % NSTAGE) * STAGE_BYTES;
#pragma unroll
        for (int kk = 0; kk < 2; kk++) {
            uint32_t ahi[2][4], alo[2][4];
#pragma unroll
            for (int ms = 0; ms < 2; ms++) {
                int r = wm + ms * 16 + (lane & 15);
                int c16 = kk * 2 + (lane >> 4);
                uint32_t off = soff32(r, c16);
                ldsm_x4(ahi[ms], sbu + S_AHI + off);
                ldsm_x4(alo[ms], sbu + S_ALO + off);
            }
#pragma unroll
            for (int p = 0; p < 4; p++) {
                int n = wn + p * 16 + ((lane >> 4) << 3) + (lane & 7);
                int c16 = kk * 2 + ((lane >> 3) & 1);
                uint32_t off = soff32(n, c16);
                uint32_t bh[4], bl[4];
                ldsm_x4(bh, sbu + S_BHI + off);
                ldsm_x4(bl, sbu + S_BLO + off);
#pragma unroll
                for (int ms = 0; ms < 2; ms++) {
                    mma16816(acc[ms][2 * p],     ahi[ms], bh[0], bh[1]);
                    mma16816(acc[ms][2 * p + 1], ahi[ms], bh[2], bh[3]);
                    mma16816(acc[ms][2 * p],     alo[ms], bh[0], bh[1]);
                    mma16816(acc[ms][2 * p + 1], alo[ms], bh[2], bh[3]);
                    mma16816(acc[ms][2 * p],     ahi[ms], bl[0], bl[1]);
                    mma16816(acc[ms][2 * p + 1], ahi[ms], bl[2], bl[3]);
                }
            }
        }
        __syncthreads();
    }

#pragma unroll
    for (int ms = 0; ms < 2; ms++) {
#pragma unroll
        for (int nt = 0; nt < 8; nt++) {
            int c = col0 + wn + nt * 8 + (lane & 3) * 2;
            float2 bi = *reinterpret_cast<const float2*>(bias + c);
            int r = row0 + wm + ms * 16 + (lane >> 2);
#pragma unroll
            for (int half = 0; half < 2; half++) {
                int rr = r + half * 8;
                if (rr >= M) continue;
                float2 v;
                v.x = acc[ms][nt][2 * half + 0] + bi.x;
                v.y = acc[ms][nt][2 * half + 1] + bi.y;
                if (EOP == 1) { v.x = fmaxf(v.x, 0.f); v.y = fmaxf(v.y, 0.f); }
                float* cp = C + (size_t)rr * Nw + c;
                if (EOP == 2) {
                    float2 o = *reinterpret_cast<const float2*>(cp);
                    v.x += o.x; v.y += o.y;
                }
                *reinterpret_cast<float2*>(cp) = v;
            }
        }
    }

    if (STATS) {
        float* ssum = reinterpret_cast<float*>(smem);
        float* ssq  = reinterpret_cast<float*>(smem) + 128;
        if (tid < 128) { ssum[tid] = 0.f; ssq[tid] = 0.f; }
        __syncthreads();
#pragma unroll
        for (int nt = 0; nt < 8; nt++) {
#pragma unroll
            for (int j = 0; j < 2; j++) {
                int cl = wn + nt * 8 + (lane & 3) * 2 + j;
                float bi = __ldg(bias + col0 + cl);
                float s = 0.f, q = 0.f;
#pragma unroll
                for (int ms = 0; ms < 2; ms++)
#pragma unroll
                    for (int half = 0; half < 2; half++) {
                        int rr = row0 + wm + ms * 16 + (lane >> 2) + half * 8;
                        float v = (rr < M) ? (acc[ms][nt][2 * half + j] + bi) : 0.f;
                        s += v; q += v * v;
                    }
                s += __shfl_down_sync(0xFFFFFFFFu, s, 16);
                s += __shfl_down_sync(0xFFFFFFFFu, s, 8);
                s += __shfl_down_sync(0xFFFFFFFFu, s, 4);
                q += __shfl_down_sync(0xFFFFFFFFu, q, 16);
                q += __shfl_down_sync(0xFFFFFFFFu, q, 8);
                q += __shfl_down_sync(0xFFFFFFFFu, q, 4);
                if ((lane >> 2) == 0) {
                    atomicAdd(&ssum[cl], s);
                    atomicAdd(&ssq[cl], q);
                }
            }
        }
        __syncthreads();
        if (tid < 128) {
            atomicAdd(&g_sum[col0 + tid], ssum[tid]);
            atomicAdd(&g_sumsq[col0 + tid], ssq[tid]);
        }
    }
}

// ---------------- host orchestration ---------------------------------------
extern "C" void kernel_launch(void* const* d_in, const int* in_sizes, int n_in,
                              void* d_out, int out_size) {
    const float* x_in    = (const float*)d_in[0];
    const int*   edge    = (const int*)d_in[1];
    const int*   se0     = (const int*)d_in[2];
    const int*   se1     = (const int*)d_in[3];
    const float* msg_w1  = (const float*)d_in[4];
    const float* msg_b1  = (const float*)d_in[5];
    const float* bn_g    = (const float*)d_in[6];
    const float* bn_b    = (const float*)d_in[7];
    const float* msg_w2  = (const float*)d_in[8];
    const float* msg_b2  = (const float*)d_in[9];
    const float* eps_gin = (const float*)d_in[10];
    const float* n2s_w1  = (const float*)d_in[11];
    const float* n2s_b1  = (const float*)d_in[12];
    const float* n2s_w2  = (const float*)d_in[13];
    const float* n2s_b2  = (const float*)d_in[14];
    const float* s2n_w1  = (const float*)d_in[15];
    const float* s2n_b1  = (const float*)d_in[16];
    const float* s2n_w2  = (const float*)d_in[17];
    const float* s2n_b2  = (const float*)d_in[18];
    const float* out_w1  = (const float*)d_in[19];
    const float* out_b1  = (const float*)d_in[20];
    const float* out_w2  = (const float*)d_in[21];
    const float* out_b2  = (const float*)d_in[22];

    float *xb, *hb, *sxb, *sxhb, *sx2b, *scaleb, *shiftb;
    __nv_bfloat16 *whi, *wlo;
    int *cnt2, *cursor2, *offsb, *partb, *csrb;
    cudaGetSymbolAddress((void**)&xb,    g_x);
    cudaGetSymbolAddress((void**)&hb,    g_h);
    cudaGetSymbolAddress((void**)&sxb,   g_sx);
    cudaGetSymbolAddress((void**)&sxhb,  g_sxh);
    cudaGetSymbolAddress((void**)&sx2b,  g_sx2);
    cudaGetSymbolAddress((void**)&scaleb, g_scale);
    cudaGetSymbolAddress((void**)&shiftb, g_shift);
    cudaGetSymbolAddress((void**)&whi,   g_whi);
    cudaGetSymbolAddress((void**)&wlo,   g_wlo);
    cudaGetSymbolAddress((void**)&cnt2,    g_cnt2);
    cudaGetSymbolAddress((void**)&cursor2, g_cursor2);
    cudaGetSymbolAddress((void**)&offsb,   g_offs);
    cudaGetSymbolAddress((void**)&partb,   g_part);
    cudaGetSymbolAddress((void**)&csrb,    g_csr);

    cudaFuncSetAttribute(k_gemm_mma<4, 0, 1>, cudaFuncAttributeMaxDynamicSharedMemorySize, GEMM_SMEM);
    cudaFuncSetAttribute(k_gemm_mma<3, 1, 0>, cudaFuncAttributeMaxDynamicSharedMemorySize, GEMM_SMEM);
    cudaFuncSetAttribute(k_gemm_mma<0, 0, 0>, cudaFuncAttributeMaxDynamicSharedMemorySize, GEMM_SMEM);
    cudaFuncSetAttribute(k_gemm_mma<1, 0, 0>, cudaFuncAttributeMaxDynamicSharedMemorySize, GEMM_SMEM);
    cudaFuncSetAttribute(k_gemm_mma<0, 1, 0>, cudaFuncAttributeMaxDynamicSharedMemorySize, GEMM_SMEM);
    cudaFuncSetAttribute(k_gemm_mma<0, 2, 0>, cudaFuncAttributeMaxDynamicSharedMemorySize, GEMM_SMEM);

    const size_t O_MSG1 = 0,       O_MSG2 = 98304,  O_N2S1 = 196608, O_N2S2 = 393216;
    const size_t O_S2N1 = 589824,  O_S2N2 = 786432, O_OUT1 = 983040, O_OUT2 = 1015808;

    const int gGS = (NSUB + 7) / 8;
    const int EB = (CSR_E + 255) / 256;

    k_hist_all<<<EB, 256>>>(edge, se0, se1, cnt2);
    k_scanA<<<NBLK_SCAN, 1024>>>(cnt2, offsb, partb);
    k_scanB<<<1, 1024>>>(partb);
    k_scanC<<<NBLK_SCAN, 1024>>>(offsb, partb, cursor2, cnt2);
    k_fill_all<<<EB, 256>>>(edge, se0, se1, cursor2, csrb);
    k_prep_all<<<(W_TOTAL + 255) / 256, 256>>>(msg_w1, msg_w2, n2s_w1, n2s_w2,
                                               s2n_w1, s2n_w2, out_w1, out_w2, whi, wlo);

    dim3 gN2(2, (N_NODES + 127) / 128);
    dim3 gN1(1, (N_NODES + 127) / 128);
    dim3 gS2(2, (NSUB + 127) / 128);
    dim3 gS1(1, (NSUB + 127) / 128);

    for (int i = 0; i < NLAYERS; i++) {
        const float* xs = (i == 0) ? x_in : xb;

        // h = [(1+eps)x + gather(x)] @ msg_w1 + b1  (GIN gather fused, + stats)
        k_gemm_mma<4, 0, 1><<<gN2, 256, GEMM_SMEM>>>(
            xs, whi + O_MSG1 + (size_t)i * HDIM * H2DIM, wlo + O_MSG1 + (size_t)i * HDIM * H2DIM,
            msg_b1 + (size_t)i * H2DIM, hb, N_NODES, HDIM, H2DIM,
            nullptr, nullptr, offsb, csrb, eps_gin, i);
        k_bnfin<<<1, 256>>>(bn_g + (size_t)i * H2DIM, bn_b + (size_t)i * H2DIM,
                            1.0f / (float)N_NODES);
        k_gemm_mma<1, 0, 0><<<gN1, 256, GEMM_SMEM>>>(
            hb, whi + O_MSG2 + (size_t)i * H2DIM * HDIM, wlo + O_MSG2 + (size_t)i * H2DIM * HDIM,
            msg_b2 + (size_t)i * HDIM, xb, N_NODES, H2DIM, HDIM,
            scaleb, shiftb, nullptr, nullptr, nullptr, 0);

        for (int s = 0; s < NSUBT; s++) {
            const int* offc = offsb + ((s == 0) ? B_S0C : B_S1C);
            const int* offr = offsb + ((s == 0) ? B_S0R : B_S1R);
            const size_t widx = (size_t)i * NSUBT + s;

            // sx[col] = sum x[row]  (standalone; sx consumed twice from 10MB buffer)
            k_gather<<<gGS, 256>>>(sxb, xb, offc, csrb, NSUB);

            k_gemm_mma<0, 1, 0><<<gS2, 256, GEMM_SMEM>>>(
                sxb, whi + O_N2S1 + widx * HDIM * H2DIM, wlo + O_N2S1 + widx * HDIM * H2DIM,
                n2s_b1 + widx * H2DIM, sxhb, NSUB, HDIM, H2DIM,
                nullptr, nullptr, nullptr, nullptr, nullptr, 0);
            k_gemm_mma<0, 0, 0><<<gS1, 256, GEMM_SMEM>>>(
                sxhb, whi + O_N2S2 + widx * H2DIM * HDIM, wlo + O_N2S2 + widx * H2DIM * HDIM,
                n2s_b2 + widx * HDIM, sx2b, NSUB, H2DIM, HDIM,
                nullptr, nullptr, nullptr, nullptr, nullptr, 0);

            // h = gather(sx2)[row] @ s2n_w1 + b1  (gatherN fused into A-fill)
            k_gemm_mma<3, 1, 0><<<gN2, 256, GEMM_SMEM>>>(
                sx2b, whi + O_S2N1 + widx * HDIM * H2DIM, wlo + O_S2N1 + widx * HDIM * H2DIM,
                s2n_b1 + widx * H2DIM, hb, N_NODES, HDIM, H2DIM,
                nullptr, nullptr, offr, csrb, nullptr, 0);
            k_gemm_mma<0, 2, 0><<<gN1, 256, GEMM_SMEM>>>(
                hb, whi + O_S2N2 + widx * H2DIM * HDIM, wlo + O_S2N2 + widx * H2DIM * HDIM,
                s2n_b2 + widx * HDIM, xb, N_NODES, H2DIM, HDIM,
                nullptr, nullptr, nullptr, nullptr, nullptr, 0);
        }
    }

    k_gemm_mma<0, 1, 0><<<gN2, 256, GEMM_SMEM>>>(
        xb, whi + O_OUT1, wlo + O_OUT1, out_b1, hb, N_NODES, HDIM, H2DIM,
        nullptr, nullptr, nullptr, nullptr, nullptr, 0);
    k_gemm_mma<0, 0, 0><<<gN1, 256, GEMM_SMEM>>>(
        hb, whi + O_OUT2, wlo + O_OUT2, out_b2, (float*)d_out, N_NODES, H2DIM, OUTDIM,
        nullptr, nullptr, nullptr, nullptr, nullptr, 0);
}

// round 16
// speedup vs baseline: 1.2610x; 1.2610x over previous
#include <cuda_runtime.h>
#include <cuda_bf16.h>
#include <cstdint>

#define N_NODES 100000
#define HDIM 128
#define H2DIM 256
#define N_EDGES 600000
#define NSUB 20000
#define ESUB 200000
#define NLAYERS 3
#define NSUBT 2
#define OUTDIM 128

#define CSR_R 340000
#define CSR_E 1400000
#define NBLK_SCAN 333
#define B_S0C 100000
#define B_S0R 120000
#define B_S1C 220000
#define B_S1R 240000

// ---------------- persistent scratch ----------------------------------------
__device__ float g_x   [N_NODES * HDIM];
__device__ float g_agg [N_NODES * HDIM];
__device__ float g_h   [N_NODES * H2DIM];
__device__ float g_msg [N_NODES * HDIM];
__device__ float g_sx  [NSUB * HDIM];
__device__ float g_sxh [NSUB * H2DIM];
__device__ float g_sx2 [NSUB * HDIM];
__device__ float g_sum  [H2DIM];
__device__ float g_sumsq[H2DIM];
__device__ float g_scale[H2DIM];
__device__ float g_shift[H2DIM];
#define W_TOTAL 1048576
__device__ __nv_bfloat16 g_whi[W_TOTAL];
__device__ __nv_bfloat16 g_wlo[W_TOTAL];
__device__ int g_cnt2   [CSR_R];
__device__ int g_cursor2[CSR_R];
__device__ int g_offs   [CSR_R + 1];
__device__ int g_part   [NBLK_SCAN + 1];
__device__ int g_csr    [CSR_E];

// ---------------- batched CSR build ------------------------------------------
__device__ __forceinline__ void edge_decode(int e, const int* __restrict__ edge,
                                            const int* __restrict__ se0,
                                            const int* __restrict__ se1,
                                            int& d, int& s) {
    if (e < N_EDGES) { d = __ldg(edge + N_EDGES + e); s = __ldg(edge + e); return; }
    e -= N_EDGES;
    if (e < ESUB) { d = B_S0C + __ldg(se0 + ESUB + e); s = __ldg(se0 + e); return; }
    e -= ESUB;
    if (e < ESUB) { d = B_S0R + __ldg(se0 + e); s = __ldg(se0 + ESUB + e); return; }
    e -= ESUB;
    if (e < ESUB) { d = B_S1C + __ldg(se1 + ESUB + e); s = __ldg(se1 + e); return; }
    e -= ESUB;
    d = B_S1R + __ldg(se1 + e); s = __ldg(se1 + ESUB + e);
}
__global__ void k_hist_all(const int* __restrict__ edge, const int* __restrict__ se0,
                           const int* __restrict__ se1, int* __restrict__ cnt) {
    int e = blockIdx.x * blockDim.x + threadIdx.x;
    if (e >= CSR_E) return;
    int d, s;
    edge_decode(e, edge, se0, se1, d, s);
    atomicAdd(&cnt[d], 1);
}
__global__ void k_fill_all(const int* __restrict__ edge, const int* __restrict__ se0,
                           const int* __restrict__ se1, int* __restrict__ cursor,
                           int* __restrict__ csr) {
    int e = blockIdx.x * blockDim.x + threadIdx.x;
    if (e >= CSR_E) return;
    int d, s;
    edge_decode(e, edge, se0, se1, d, s);
    int pos = atomicAdd(&cursor[d], 1);
    csr[pos] = s;
}
__device__ __forceinline__ int block_excl_scan(int v) {
    __shared__ int ws[32];
    int lane = threadIdx.x & 31, w = threadIdx.x >> 5;
    int x = v;
#pragma unroll
    for (int d = 1; d < 32; d <<= 1) {
        int y = __shfl_up_sync(0xFFFFFFFFu, x, d);
        if (lane >= d) x += y;
    }
    if (lane == 31) ws[w] = x;
    __syncthreads();
    if (w == 0) {
        int s = ws[lane];
#pragma unroll
        for (int d = 1; d < 32; d <<= 1) {
            int y = __shfl_up_sync(0xFFFFFFFFu, s, d);
            if (lane >= d) s += y;
        }
        ws[lane] = s;
    }
    __syncthreads();
    int woff = (w > 0) ? ws[w - 1] : 0;
    return x - v + woff;
}
__global__ void k_scanA(const int* __restrict__ cnt, int* __restrict__ offs,
                        int* __restrict__ part) {
    int idx = blockIdx.x * 1024 + threadIdx.x;
    int v = (idx < CSR_R) ? cnt[idx] : 0;
    int excl = block_excl_scan(v);
    if (idx < CSR_R) offs[idx] = excl;
    if (threadIdx.x == 1023) part[blockIdx.x] = excl + v;
}
__global__ void k_scanB(int* __restrict__ part) {
    int i = threadIdx.x;
    int v = (i < NBLK_SCAN) ? part[i] : 0;
    int excl = block_excl_scan(v);
    __syncthreads();
    if (i < NBLK_SCAN) part[i] = excl;
    if (i == NBLK_SCAN - 1) part[NBLK_SCAN] = excl + v;
}
// scanC also restores cnt2 to zero (consumed by scanA) for the next replay.
__global__ void k_scanC(int* __restrict__ offs, const int* __restrict__ part,
                        int* __restrict__ cursor, int* __restrict__ cnt) {
    int idx = blockIdx.x * 1024 + threadIdx.x;
    if (idx < CSR_R) {
        int o = offs[idx] + part[blockIdx.x];
        offs[idx] = o;
        cursor[idx] = o;
        cnt[idx] = 0;
    } else if (idx == CSR_R) {
        offs[CSR_R] = part[NBLK_SCAN];
    }
}

// ---------------- gather (unroll 4) -------------------------------------------
template <int BASE>
__global__ void k_gather(float* __restrict__ out, const float* __restrict__ in,
                         const int* __restrict__ offs, const int* __restrict__ srcs,
                         const float* __restrict__ basex, const float* __restrict__ eps,
                         int layer, int nrows) {
    int node = blockIdx.x * 8 + (threadIdx.x >> 5);
    if (node >= nrows) return;
    int lane4 = (threadIdx.x & 31) * 4;
    int b = __ldg(offs + node), e = __ldg(offs + node + 1);
    float4 acc;
    if (BASE == 1) {
        float cf = 1.0f + __ldg(eps + layer);
        float4 v = *reinterpret_cast<const float4*>(basex + (size_t)node * HDIM + lane4);
        acc = make_float4(cf * v.x, cf * v.y, cf * v.z, cf * v.w);
    } else {
        acc = make_float4(0.f, 0.f, 0.f, 0.f);
    }
    int j = b;
    for (; j + 4 <= e; j += 4) {
        int s0 = __ldg(srcs + j + 0), s1 = __ldg(srcs + j + 1);
        int s2 = __ldg(srcs + j + 2), s3 = __ldg(srcs + j + 3);
        float4 v0 = *reinterpret_cast<const float4*>(in + (size_t)s0 * HDIM + lane4);
        float4 v1 = *reinterpret_cast<const float4*>(in + (size_t)s1 * HDIM + lane4);
        float4 v2 = *reinterpret_cast<const float4*>(in + (size_t)s2 * HDIM + lane4);
        float4 v3 = *reinterpret_cast<const float4*>(in + (size_t)s3 * HDIM + lane4);
        acc.x += (v0.x + v1.x) + (v2.x + v3.x);
        acc.y += (v0.y + v1.y) + (v2.y + v3.y);
        acc.z += (v0.z + v1.z) + (v2.z + v3.z);
        acc.w += (v0.w + v1.w) + (v2.w + v3.w);
    }
    for (; j < e; j++) {
        int s = __ldg(srcs + j);
        float4 v = *reinterpret_cast<const float4*>(in + (size_t)s * HDIM + lane4);
        acc.x += v.x; acc.y += v.y; acc.z += v.z; acc.w += v.w;
    }
    *reinterpret_cast<float4*>(out + (size_t)node * HDIM + lane4) = acc;
}

// ---------------- BN finalize ---------------------------------------------------
__global__ void k_bnfin(const float* __restrict__ gamma, const float* __restrict__ beta,
                        float invM) {
    int c = threadIdx.x;
    float mean = g_sum[c] * invM;
    float var  = g_sumsq[c] * invM - mean * mean;
    float sc   = __ldg(gamma + c) * rsqrtf(var + 1e-5f);
    g_scale[c] = sc;
    g_shift[c] = __ldg(beta + c) - mean * sc;
    g_sum[c] = 0.f;
    g_sumsq[c] = 0.f;
}

// ---------------- single-launch weight prep (also zeroes BN stats) -----------
__global__ void k_prep_all(const float* __restrict__ w0, const float* __restrict__ w1,
                           const float* __restrict__ w2, const float* __restrict__ w3,
                           const float* __restrict__ w4, const float* __restrict__ w5,
                           const float* __restrict__ w6, const float* __restrict__ w7,
                           __nv_bfloat16* __restrict__ hi, __nv_bfloat16* __restrict__ lo) {
    int i = blockIdx.x * blockDim.x + threadIdx.x;
    if (i < H2DIM) { g_sum[i] = 0.f; g_sumsq[i] = 0.f; }
    if (i >= W_TOTAL) return;
    const float* src;
    int base, K, Nw;
    if      (i < 98304)   { src = w0; base = 0;       K = 128; Nw = 256; }
    else if (i < 196608)  { src = w1; base = 98304;   K = 256; Nw = 128; }
    else if (i < 393216)  { src = w2; base = 196608;  K = 128; Nw = 256; }
    else if (i < 589824)  { src = w3; base = 393216;  K = 256; Nw = 128; }
    else if (i < 786432)  { src = w4; base = 589824;  K = 128; Nw = 256; }
    else if (i < 983040)  { src = w5; base = 786432;  K = 256; Nw = 128; }
    else if (i < 1015808) { src = w6; base = 983040;  K = 128; Nw = 256; }
    else                  { src = w7; base = 1015808; K = 256; Nw = 128; }
    int local = i - base;
    int per = K * Nw;
    int m = local / per, r = local % per;
    int k = r / Nw, n = r % Nw;
    float w = __ldg(src + local);
    __nv_bfloat16 h = __float2bfloat16(w);
    float res = w - __bfloat162float(h);
    int o = base + m * per + n * K + k;
    hi[o] = h;
    lo[o] = __float2bfloat16(res);
}

// ---------------- mma.sync helpers ------------------------------------------
__device__ __forceinline__ uint32_t smem_u32(const void* p) {
    uint32_t a;
    asm("{ .reg .u64 t; cvta.to.shared.u64 t, %1; cvt.u32.u64 %0, t; }" : "=r"(a) : "l"(p));
    return a;
}
__device__ __forceinline__ void ldsm_x4(uint32_t* r, uint32_t addr) {
    asm volatile("ldmatrix.sync.aligned.m8n8.x4.shared.b16 {%0,%1,%2,%3}, [%4];"
                 : "=r"(r[0]), "=r"(r[1]), "=r"(r[2]), "=r"(r[3]) : "r"(addr));
}
__device__ __forceinline__ void mma16816(float* d, const uint32_t* a, uint32_t b0, uint32_t b1) {
    asm volatile(
        "mma.sync.aligned.m16n8k16.row.col.f32.bf16.bf16.f32 "
        "{%0,%1,%2,%3}, {%4,%5,%6,%7}, {%8,%9}, {%0,%1,%2,%3};"
        : "+f"(d[0]), "+f"(d[1]), "+f"(d[2]), "+f"(d[3])
        : "r"(a[0]), "r"(a[1]), "r"(a[2]), "r"(a[3]), "r"(b0), "r"(b1));
}
__device__ __forceinline__ void cp_async16(uint32_t dst, const void* src) {
    asm volatile("cp.async.cg.shared.global [%0], [%1], 16;" :: "r"(dst), "l"(src));
}
__device__ __forceinline__ uint32_t soff32(int r, int c16) {
    return (uint32_t)r * 64u + (uint32_t)((c16 ^ ((r >> 1) & 3)) << 4);
}
__device__ __forceinline__ void split2(float x, float y, uint32_t& hp, uint32_t& lp) {
    __nv_bfloat162 h = __float22bfloat162_rn(make_float2(x, y));
    float2 f = __bfloat1622float2(h);
    __nv_bfloat162 l = __float22bfloat162_rn(make_float2(x - f.x, y - f.y));
    hp = *(uint32_t*)&h;
    lp = *(uint32_t*)&l;
}

// ---------------- pipelined mma.sync split-bf16 GEMM -------------------------
// 3-stage cp.async pipeline, K=32 per stage, 32KB/stage -> 96KB total.
// 2 CTAs x 96KB = 192KB <= 228KB SM limit: occupancy 2 preserved.
#define S_AHI 0
#define S_ALO 8192
#define S_BHI 16384
#define S_BLO 24576
#define STAGE_BYTES 32768
#define NSTAGE 3
#define GEMM_SMEM (STAGE_BYTES * NSTAGE)

template <int AOP, int EOP, int STATS>
__global__ __launch_bounds__(256, 2) void k_gemm_mma(
    const float* __restrict__ A, const __nv_bfloat16* __restrict__ Bhi,
    const __nv_bfloat16* __restrict__ Blo, const float* __restrict__ bias,
    float* __restrict__ C, int M, int K, int Nw,
    const float* __restrict__ scale, const float* __restrict__ shift) {
    extern __shared__ char smem[];
    const uint32_t sbase = smem_u32(smem);
    const int tid = threadIdx.x;
    const int wid = tid >> 5;
    const int lane = tid & 31;
    const int row0 = blockIdx.y * 128;
    const int col0 = blockIdx.x * 128;
    const int wm = (wid & 3) * 32;
    const int wn = (wid >> 2) * 64;

    float acc[2][8][4];
#pragma unroll
    for (int i = 0; i < 2; i++)
#pragma unroll
        for (int j = 0; j < 8; j++)
#pragma unroll
            for (int q = 0; q < 4; q++) acc[i][j][q] = 0.f;

    auto fill = [&](int s) {
        int buf = s % NSTAGE;
        char* sb = smem + buf * STAGE_BYTES;
        uint32_t sbu = sbase + (uint32_t)buf * STAGE_BYTES;
        int kof = s * 32;
#pragma unroll
        for (int it = 0; it < 2; it++) {
            int task = tid + it * 256;
            int r = task >> 2, c16 = task & 3;
            uint32_t so = soff32(r, c16);
            cp_async16(sbu + S_BHI + so, Bhi + (size_t)(col0 + r) * K + kof + c16 * 8);
            cp_async16(sbu + S_BLO + so, Blo + (size_t)(col0 + r) * K + kof + c16 * 8);
        }
#pragma unroll
        for (int it = 0; it < 2; it++) {
            int task = tid + it * 256;
            int r = task >> 2, c16 = task & 3;
            uint32_t so = soff32(r, c16);
            float4 v0 = make_float4(0.f, 0.f, 0.f, 0.f), v1 = v0;
            if (row0 + r < M) {
                const float* ap = A + (size_t)(row0 + r) * K + kof + c16 * 8;
                v0 = *reinterpret_cast<const float4*>(ap);
                v1 = *reinterpret_cast<const float4*>(ap + 4);
                if (AOP == 1) {
                    int gk = kof + c16 * 8;
                    float4 sc0 = *reinterpret_cast<const float4*>(scale + gk);
                    float4 sc1 = *reinterpret_cast<const float4*>(scale + gk + 4);
                    float4 sh0 = *reinterpret_cast<const float4*>(shift + gk);
                    float4 sh1 = *reinterpret_cast<const float4*>(shift + gk + 4);
                    v0.x = fmaxf(fmaf(v0.x, sc0.x, sh0.x), 0.f);
                    v0.y = fmaxf(fmaf(v0.y, sc0.y, sh0.y), 0.f);
                    v0.z = fmaxf(fmaf(v0.z, sc0.z, sh0.z), 0.f);
                    v0.w = fmaxf(fmaf(v0.w, sc0.w, sh0.w), 0.f);
                    v1.x = fmaxf(fmaf(v1.x, sc1.x, sh1.x), 0.f);
                    v1.y = fmaxf(fmaf(v1.y, sc1.y, sh1.y), 0.f);
                    v1.z = fmaxf(fmaf(v1.z, sc1.z, sh1.z), 0.f);
                    v1.w = fmaxf(fmaf(v1.w, sc1.w, sh1.w), 0.f);
                }
            }
            uint32_t h0, l0, h1, l1, h2, l2, h3, l3;
            split2(v0.x, v0.y, h0, l0);
            split2(v0.z, v0.w, h1, l1);
            split2(v1.x, v1.y, h2, l2);
            split2(v1.z, v1.w, h3, l3);
            *reinterpret_cast<uint4*>(sb + S_AHI + so) = make_uint4(h0, h1, h2, h3);
            *reinterpret_cast<uint4*>(sb + S_ALO + so) = make_uint4(l0, l1, l2, l3);
        }
        asm volatile("cp.async.commit_group;" ::: "memory");
    };

    const int nst = K >> 5;
    fill(0);
    if (nst > 1) fill(1);
    for (int s = 0; s < nst; s++) {
        if (s + 2 < nst) {
            fill(s + 2);
            asm volatile("cp.async.wait_group 2;" ::: "memory");
        } else if (s + 1 < nst) {
            asm volatile("cp.async.wait_group 1;" ::: "memory");
        } else {
            asm volatile("cp.async.wait_group 0;" ::: "memory");
        }
        __syncthreads();

        uint32_t sbu = sbase + (uint32_t)(s % NSTAGE) * STAGE_BYTES;
#pragma unroll
        for (int kk = 0; kk < 2; kk++) {
            uint32_t ahi[2][4], alo[2][4];
#pragma unroll
            for (int ms = 0; ms < 2; ms++) {
                int r = wm + ms * 16 + (lane & 15);
                int c16 = kk * 2 + (lane >> 4);
                uint32_t off = soff32(r, c16);
                ldsm_x4(ahi[ms], sbu + S_AHI + off);
                ldsm_x4(alo[ms], sbu + S_ALO + off);
            }
#pragma unroll
            for (int p = 0; p < 4; p++) {
                int n = wn + p * 16 + ((lane >> 4) << 3) + (lane & 7);
                int c16 = kk * 2 + ((lane >> 3) & 1);
                uint32_t off = soff32(n, c16);
                uint32_t bh[4], bl[4];
                ldsm_x4(bh, sbu + S_BHI + off);
                ldsm_x4(bl, sbu + S_BLO + off);
#pragma unroll
                for (int ms = 0; ms < 2; ms++) {
                    mma16816(acc[ms][2 * p],     ahi[ms], bh[0], bh[1]);
                    mma16816(acc[ms][2 * p + 1], ahi[ms], bh[2], bh[3]);
                    mma16816(acc[ms][2 * p],     alo[ms], bh[0], bh[1]);
                    mma16816(acc[ms][2 * p + 1], alo[ms], bh[2], bh[3]);
                    mma16816(acc[ms][2 * p],     ahi[ms], bl[0], bl[1]);
                    mma16816(acc[ms][2 * p + 1], ahi[ms], bl[2], bl[3]);
                }
            }
        }
        __syncthreads();
    }

#pragma unroll
    for (int ms = 0; ms < 2; ms++) {
#pragma unroll
        for (int nt = 0; nt < 8; nt++) {
            int c = col0 + wn + nt * 8 + (lane & 3) * 2;
            float2 bi = *reinterpret_cast<const float2*>(bias + c);
            int r = row0 + wm + ms * 16 + (lane >> 2);
#pragma unroll
            for (int half = 0; half < 2; half++) {
                int rr = r + half * 8;
                if (rr >= M) continue;
                float2 v;
                v.x = acc[ms][nt][2 * half + 0] + bi.x;
                v.y = acc[ms][nt][2 * half + 1] + bi.y;
                if (EOP == 1) { v.x = fmaxf(v.x, 0.f); v.y = fmaxf(v.y, 0.f); }
                float* cp = C + (size_t)rr * Nw + c;
                if (EOP == 2) {
                    float2 o = *reinterpret_cast<const float2*>(cp);
                    v.x += o.x; v.y += o.y;
                }
                *reinterpret_cast<float2*>(cp) = v;
            }
        }
    }

    if (STATS) {
        float* ssum = reinterpret_cast<float*>(smem);
        float* ssq  = reinterpret_cast<float*>(smem) + 128;
        if (tid < 128) { ssum[tid] = 0.f; ssq[tid] = 0.f; }
        __syncthreads();
#pragma unroll
        for (int nt = 0; nt < 8; nt++) {
#pragma unroll
            for (int j = 0; j < 2; j++) {
                int cl = wn + nt * 8 + (lane & 3) * 2 + j;
                float bi = __ldg(bias + col0 + cl);
                float s = 0.f, q = 0.f;
#pragma unroll
                for (int ms = 0; ms < 2; ms++)
#pragma unroll
                    for (int half = 0; half < 2; half++) {
                        int rr = row0 + wm + ms * 16 + (lane >> 2) + half * 8;
                        float v = (rr < M) ? (acc[ms][nt][2 * half + j] + bi) : 0.f;
                        s += v; q += v * v;
                    }
                s += __shfl_down_sync(0xFFFFFFFFu, s, 16);
                s += __shfl_down_sync(0xFFFFFFFFu, s, 8);
                s += __shfl_down_sync(0xFFFFFFFFu, s, 4);
                q += __shfl_down_sync(0xFFFFFFFFu, q, 16);
                q += __shfl_down_sync(0xFFFFFFFFu, q, 8);
                q += __shfl_down_sync(0xFFFFFFFFu, q, 4);
                if ((lane >> 2) == 0) {
                    atomicAdd(&ssum[cl], s);
                    atomicAdd(&ssq[cl], q);
                }
            }
        }
        __syncthreads();
        if (tid < 128) {
            atomicAdd(&g_sum[col0 + tid], ssum[tid]);
            atomicAdd(&g_sumsq[col0 + tid], ssq[tid]);
        }
    }
}

// ---------------- host orchestration ---------------------------------------
extern "C" void kernel_launch(void* const* d_in, const int* in_sizes, int n_in,
                              void* d_out, int out_size) {
    const float* x_in    = (const float*)d_in[0];
    const int*   edge    = (const int*)d_in[1];
    const int*   se0     = (const int*)d_in[2];
    const int*   se1     = (const int*)d_in[3];
    const float* msg_w1  = (const float*)d_in[4];
    const float* msg_b1  = (const float*)d_in[5];
    const float* bn_g    = (const float*)d_in[6];
    const float* bn_b    = (const float*)d_in[7];
    const float* msg_w2  = (const float*)d_in[8];
    const float* msg_b2  = (const float*)d_in[9];
    const float* eps_gin = (const float*)d_in[10];
    const float* n2s_w1  = (const float*)d_in[11];
    const float* n2s_b1  = (const float*)d_in[12];
    const float* n2s_w2  = (const float*)d_in[13];
    const float* n2s_b2  = (const float*)d_in[14];
    const float* s2n_w1  = (const float*)d_in[15];
    const float* s2n_b1  = (const float*)d_in[16];
    const float* s2n_w2  = (const float*)d_in[17];
    const float* s2n_b2  = (const float*)d_in[18];
    const float* out_w1  = (const float*)d_in[19];
    const float* out_b1  = (const float*)d_in[20];
    const float* out_w2  = (const float*)d_in[21];
    const float* out_b2  = (const float*)d_in[22];

    float *xb, *aggb, *hb, *msgb, *sxb, *sxhb, *sx2b, *scaleb, *shiftb;
    __nv_bfloat16 *whi, *wlo;
    int *cnt2, *cursor2, *offsb, *partb, *csrb;
    cudaGetSymbolAddress((void**)&xb,    g_x);
    cudaGetSymbolAddress((void**)&aggb,  g_agg);
    cudaGetSymbolAddress((void**)&hb,    g_h);
    cudaGetSymbolAddress((void**)&msgb,  g_msg);
    cudaGetSymbolAddress((void**)&sxb,   g_sx);
    cudaGetSymbolAddress((void**)&sxhb,  g_sxh);
    cudaGetSymbolAddress((void**)&sx2b,  g_sx2);
    cudaGetSymbolAddress((void**)&scaleb, g_scale);
    cudaGetSymbolAddress((void**)&shiftb, g_shift);
    cudaGetSymbolAddress((void**)&whi,   g_whi);
    cudaGetSymbolAddress((void**)&wlo,   g_wlo);
    cudaGetSymbolAddress((void**)&cnt2,    g_cnt2);
    cudaGetSymbolAddress((void**)&cursor2, g_cursor2);
    cudaGetSymbolAddress((void**)&offsb,   g_offs);
    cudaGetSymbolAddress((void**)&partb,   g_part);
    cudaGetSymbolAddress((void**)&csrb,    g_csr);

    cudaFuncSetAttribute(k_gemm_mma<0, 0, 1>, cudaFuncAttributeMaxDynamicSharedMemorySize, GEMM_SMEM);
    cudaFuncSetAttribute(k_gemm_mma<0, 0, 0>, cudaFuncAttributeMaxDynamicSharedMemorySize, GEMM_SMEM);
    cudaFuncSetAttribute(k_gemm_mma<1, 0, 0>, cudaFuncAttributeMaxDynamicSharedMemorySize, GEMM_SMEM);
    cudaFuncSetAttribute(k_gemm_mma<0, 1, 0>, cudaFuncAttributeMaxDynamicSharedMemorySize, GEMM_SMEM);
    cudaFuncSetAttribute(k_gemm_mma<0, 2, 0>, cudaFuncAttributeMaxDynamicSharedMemorySize, GEMM_SMEM);

    const size_t O_MSG1 = 0,       O_MSG2 = 98304,  O_N2S1 = 196608, O_N2S2 = 393216;
    const size_t O_S2N1 = 589824,  O_S2N2 = 786432, O_OUT1 = 983040, O_OUT2 = 1015808;

    const int gGN = (N_NODES + 7) / 8;
    const int gGS = (NSUB + 7) / 8;
    const int EB = (CSR_E + 255) / 256;

    k_hist_all<<<EB, 256>>>(edge, se0, se1, cnt2);
    k_scanA<<<NBLK_SCAN, 1024>>>(cnt2, offsb, partb);
    k_scanB<<<1, 1024>>>(partb);
    k_scanC<<<NBLK_SCAN, 1024>>>(offsb, partb, cursor2, cnt2);
    k_fill_all<<<EB, 256>>>(edge, se0, se1, cursor2, csrb);
    k_gather<1><<<gGN, 256>>>(aggb, x_in, offsb, csrb, x_in, eps_gin, 0, N_NODES);
    k_prep_all<<<(W_TOTAL + 255) / 256, 256>>>(msg_w1, msg_w2, n2s_w1, n2s_w2,
                                               s2n_w1, s2n_w2, out_w1, out_w2, whi, wlo);

    dim3 gN2(2, (N_NODES + 127) / 128);
    dim3 gN1(1, (N_NODES + 127) / 128);
    dim3 gS2(2, (NSUB + 127) / 128);
    dim3 gS1(1, (NSUB + 127) / 128);

    for (int i = 0; i < NLAYERS; i++) {
        if (i > 0)
            k_gather<1><<<gGN, 256>>>(aggb, xb, offsb, csrb, xb, eps_gin, i, N_NODES);

        k_gemm_mma<0, 0, 1><<<gN2, 256, GEMM_SMEM>>>(
            aggb, whi + O_MSG1 + (size_t)i * HDIM * H2DIM, wlo + O_MSG1 + (size_t)i * HDIM * H2DIM,
            msg_b1 + (size_t)i * H2DIM, hb, N_NODES, HDIM, H2DIM, nullptr, nullptr);
        k_bnfin<<<1, 256>>>(bn_g + (size_t)i * H2DIM, bn_b + (size_t)i * H2DIM,
                            1.0f / (float)N_NODES);
        k_gemm_mma<1, 0, 0><<<gN1, 256, GEMM_SMEM>>>(
            hb, whi + O_MSG2 + (size_t)i * H2DIM * HDIM, wlo + O_MSG2 + (size_t)i * H2DIM * HDIM,
            msg_b2 + (size_t)i * HDIM, xb, N_NODES, H2DIM, HDIM, scaleb, shiftb);

        for (int s = 0; s < NSUBT; s++) {
            const int* offc = offsb + ((s == 0) ? B_S0C : B_S1C);
            const int* offr = offsb + ((s == 0) ? B_S0R : B_S1R);
            const size_t widx = (size_t)i * NSUBT + s;

            k_gather<0><<<gGS, 256>>>(sxb, xb, offc, csrb, nullptr, nullptr, 0, NSUB);

            k_gemm_mma<0, 1, 0><<<gS2, 256, GEMM_SMEM>>>(
                sxb, whi + O_N2S1 + widx * HDIM * H2DIM, wlo + O_N2S1 + widx * HDIM * H2DIM,
                n2s_b1 + widx * H2DIM, sxhb, NSUB, HDIM, H2DIM, nullptr, nullptr);
            k_gemm_mma<0, 0, 0><<<gS1, 256, GEMM_SMEM>>>(
                sxhb, whi + O_N2S2 + widx * H2DIM * HDIM, wlo + O_N2S2 + widx * H2DIM * HDIM,
                n2s_b2 + widx * HDIM, sx2b, NSUB, H2DIM, HDIM, nullptr, nullptr);

            k_gather<0><<<gGN, 256>>>(msgb, sx2b, offr, csrb, nullptr, nullptr, 0, N_NODES);

            k_gemm_mma<0, 1, 0><<<gN2, 256, GEMM_SMEM>>>(
                msgb, whi + O_S2N1 + widx * HDIM * H2DIM, wlo + O_S2N1 + widx * HDIM * H2DIM,
                s2n_b1 + widx * H2DIM, hb, N_NODES, HDIM, H2DIM, nullptr, nullptr);
            k_gemm_mma<0, 2, 0><<<gN1, 256, GEMM_SMEM>>>(
                hb, whi + O_S2N2 + widx * H2DIM * HDIM, wlo + O_S2N2 + widx * H2DIM * HDIM,
                s2n_b2 + widx * HDIM, xb, N_NODES, H2DIM, HDIM, nullptr, nullptr);
        }
    }

    k_gemm_mma<0, 1, 0><<<gN2, 256, GEMM_SMEM>>>(
        xb, whi + O_OUT1, wlo + O_OUT1, out_b1, hb, N_NODES, HDIM, H2DIM, nullptr, nullptr);
    k_gemm_mma<0, 0, 0><<<gN1, 256, GEMM_SMEM>>>(
        hb, whi + O_OUT2, wlo + O_OUT2, out_b2, (float*)d_out,
        N_NODES, H2DIM, OUTDIM, nullptr, nullptr);
}